// round 17
// baseline (speedup 1.0000x reference)
#include <cuda_runtime.h>
#include <cuda_fp16.h>
#include <cstdint>
#include <math.h>

// DeformAttn via ldmatrix + mma.sync (m16n8k16 fp16, fp32 accum) — base sm_103 ISA.
// Round 17: split-pass sample pipeline with TRIPLE-buffered x slices:
//   iteration s:  projK(s+1) -> softmax(s+1) -> projV(s) -> acc(s) -> store(s+2) -> bar
// The softmax shfl/exp chain is sandwiched between two MMA chains in one basic
// block, so ptxas fills its latency with projV's ldsm/MMA issue (tensor no longer
// idles through the softmax tail). kp/vp are never co-live (peak regs lower).
// Champion pieces kept: prep_w ks-major affine W + cp.async staging, persistent
// CTAs, group barriers, packed uint2 staging stores.

namespace {
constexpr int Bn = 4, Cn = 128, Sn = 9, Dn = 16384;
constexpr int D_TILE = 64;
constexpr int NT = 256;
constexpr int N_TILES = (Dn / D_TILE) * Bn;   // 1024
constexpr int GRID_X = 152;
constexpr float ATT_SCALE = 0.25f;

constexpr int SM_WQ = 0;            // 3 x 32KB ks-major fp16 W
constexpr int SM_WK = 32768;
constexpr int SM_WV = 65536;
constexpr int SM_X  = 98304;        // 3 buffers x [group 0/1] 8KB slices = 48KB
constexpr int SM_TOTAL = 147456;    // 144KB
}

__device__ __align__(16) char g_wh[3 * 32768];

__device__ __forceinline__ uint32_t smem_u32(const void* p) {
    uint32_t a;
    asm("{ .reg .u64 t; cvta.to.shared.u64 t, %1; cvt.u32.u64 %0, t; }" : "=r"(a) : "l"(p));
    return a;
}
__device__ __forceinline__ uint32_t h2_bits(__half2 h) {
    return *reinterpret_cast<uint32_t*>(&h);
}
// x slice rows: 64B (32 halfwords), 16B chunks XOR-swizzled by (row>>1)&3 (ks-affine)
__device__ __forceinline__ uint32_t swzX(int row, int colh) {
    int chunk = ((colh >> 3) & 3) ^ ((row >> 1) & 3);
    return (uint32_t)(row * 64 + chunk * 16 + (colh & 7) * 2);
}
__device__ __forceinline__ void ldsm4(uint32_t r[4], uint32_t addr) {
    asm volatile("ldmatrix.sync.aligned.m8n8.x4.shared.b16 {%0,%1,%2,%3}, [%4];"
                 : "=r"(r[0]), "=r"(r[1]), "=r"(r[2]), "=r"(r[3]) : "r"(addr));
}
__device__ __forceinline__ void ldsm4t(uint32_t r[4], uint32_t addr) {
    asm volatile("ldmatrix.sync.aligned.m8n8.x4.trans.shared.b16 {%0,%1,%2,%3}, [%4];"
                 : "=r"(r[0]), "=r"(r[1]), "=r"(r[2]), "=r"(r[3]) : "r"(addr));
}
__device__ __forceinline__ void mma16816(float d[4], const uint32_t a[4], const uint32_t b[2]) {
    asm volatile(
        "mma.sync.aligned.m16n8k16.row.col.f32.f16.f16.f32 "
        "{%0,%1,%2,%3},{%4,%5,%6,%7},{%8,%9},{%0,%1,%2,%3};"
        : "+f"(d[0]), "+f"(d[1]), "+f"(d[2]), "+f"(d[3])
        : "r"(a[0]), "r"(a[1]), "r"(a[2]), "r"(a[3]), "r"(b[0]), "r"(b[1]));
}
__device__ __forceinline__ void grp_bar(int g) {
    asm volatile("bar.sync %0, 128;" :: "r"(g + 1) : "memory");
}

// ---- prep kernel: W fp32 [o][c] -> ks-major conflict-free fp16 scratch ----
__global__ void prep_w(const float* __restrict__ Wq, const float* __restrict__ Wk,
                       const float* __restrict__ Wv) {
    const int t = blockIdx.x * 256 + threadIdx.x;   // 0..12287
    const int w = t >> 12;
    const int rem = t & 4095;
    const int o = rem >> 5, f4 = rem & 31;
    const float* W = (w == 0) ? Wq : (w == 1) ? Wk : Wv;
    const float4 v = *reinterpret_cast<const float4*>(W + o * 128 + f4 * 4);
    const int ks = f4 >> 2;
    const int half = (f4 >> 1) & 1;
    const int pos = (f4 & 1) * 4;
    char* dst = g_wh + w * 32768 + ks * 4096 + o * 32
              + ((half ^ ((o >> 2) & 1)) << 4) + pos * 2;
    *reinterpret_cast<__half2*>(dst)     = __floats2half2_rn(v.x, v.y);
    *reinterpret_cast<__half2*>(dst + 4) = __floats2half2_rn(v.z, v.w);
}

// ---- per-group x slice staging: 128 threads stage [128c x 32d] fp32 -> fp16 ----
__device__ __forceinline__ void pf_load(float4 pf[8], const float* __restrict__ src,
                                        long cstride, int wt) {
#pragma unroll
    for (int i = 0; i < 8; i++) {
        const int g = i * 128 + wt;
        const int c = g >> 3, d4 = (g & 7) * 4;
        pf[i] = *reinterpret_cast<const float4*>(src + (long)c * cstride + d4);
    }
}
__device__ __forceinline__ void pf_store(char* xb, const float4 pf[8], int wt) {
#pragma unroll
    for (int i = 0; i < 8; i++) {
        const int g = i * 128 + wt;
        const int c = g >> 3, d4 = (g & 7) * 4;
        const uint32_t off = swzX(c, d4);
        uint2 pk;
        pk.x = h2_bits(__floats2half2_rn(pf[i].x, pf[i].y));
        pk.y = h2_bits(__floats2half2_rn(pf[i].z, pf[i].w));
        *reinterpret_cast<uint2*>(xb + off) = pk;
    }
}

// single projection (Wq/Wk/Wv selectable), warp tile m32 x n32, affine A addresses
__device__ __forceinline__ void proj(uint32_t wb, uint32_t xb,
                                     uint32_t aw0, uint32_t aw1,
                                     int b_crem, int b_drem, float acc[2][4][4]) {
#pragma unroll
    for (int t = 0; t < 2; t++)
#pragma unroll
        for (int n = 0; n < 4; n++)
#pragma unroll
            for (int i = 0; i < 4; i++) acc[t][n][i] = 0.0f;
#pragma unroll
    for (int ks = 0; ks < 8; ks++) {
        uint32_t a[2][4];
        ldsm4(a[0], wb + ks * 4096 + aw0);
        ldsm4(a[1], wb + ks * 4096 + aw1);
        const int c = ks * 16 + b_crem;
        uint32_t bf[4][2];
#pragma unroll
        for (int np = 0; np < 2; np++) {
            uint32_t r4[4];
            ldsm4t(r4, xb + swzX(c, np * 16 + b_drem));
            bf[np * 2][0] = r4[0]; bf[np * 2][1] = r4[1];
            bf[np * 2 + 1][0] = r4[2]; bf[np * 2 + 1][1] = r4[3];
        }
#pragma unroll
        for (int t = 0; t < 2; t++)
#pragma unroll
            for (int n = 0; n < 4; n++) mma16816(acc[t][n], a[t], bf[n]);
    }
}

// softmax weights for one sample from kp (updates den)
__device__ __forceinline__ void softmax_head(const float qp[2][4][4],
                                             const float kp[2][4][4],
                                             float w[2][4][2], float den[2][4][2]) {
#pragma unroll
    for (int t = 0; t < 2; t++)
#pragma unroll
        for (int n = 0; n < 4; n++) {
            float pe = qp[t][n][0] * kp[t][n][0] + qp[t][n][2] * kp[t][n][2];
            float po = qp[t][n][1] * kp[t][n][1] + qp[t][n][3] * kp[t][n][3];
            pe += __shfl_xor_sync(0xffffffffu, pe, 4);
            pe += __shfl_xor_sync(0xffffffffu, pe, 8);
            pe += __shfl_xor_sync(0xffffffffu, pe, 16);
            po += __shfl_xor_sync(0xffffffffu, po, 4);
            po += __shfl_xor_sync(0xffffffffu, po, 8);
            po += __shfl_xor_sync(0xffffffffu, po, 16);
            const float we = __expf(ATT_SCALE * pe);
            const float wo = __expf(ATT_SCALE * po);
            w[t][n][0] = we; w[t][n][1] = wo;
            den[t][n][0] += we; den[t][n][1] += wo;
        }
}
__device__ __forceinline__ void acc_apply(float acc[2][4][4], const float w[2][4][2],
                                          const float vp[2][4][4]) {
#pragma unroll
    for (int t = 0; t < 2; t++)
#pragma unroll
        for (int n = 0; n < 4; n++) {
            acc[t][n][0] = fmaf(w[t][n][0], vp[t][n][0], acc[t][n][0]);
            acc[t][n][1] = fmaf(w[t][n][1], vp[t][n][1], acc[t][n][1]);
            acc[t][n][2] = fmaf(w[t][n][0], vp[t][n][2], acc[t][n][2]);
            acc[t][n][3] = fmaf(w[t][n][1], vp[t][n][3], acc[t][n][3]);
        }
}

__global__ void __launch_bounds__(NT, 1)
deform_attn_hmma(const float* __restrict__ q,  const float* __restrict__ kv,
                 const float* __restrict__ bq, const float* __restrict__ bv,
                 float* __restrict__ out)
{
    extern __shared__ char smem[];
    const uint32_t sb = smem_u32(smem);
    const int tid = threadIdx.x, lane = tid & 31, wid = tid >> 5;
    const int warp_m = wid & 3;
    const int grp = wid >> 2;           // warpgroup: d-slice [0,32) or [32,64)
    const int wt = tid & 127;

    // affine A-fragment offsets (per-thread constants)
    const int row0 = warp_m * 32 + (lane & 7) + ((lane >> 3) & 1) * 8;
    const int row1 = row0 + 16;
    const int ahalf = lane >> 4;
    const uint32_t aw0 = (uint32_t)(row0 * 32 + ((ahalf ^ ((row0 >> 2) & 1)) << 4));
    const uint32_t aw1 = (uint32_t)(row1 * 32 + ((ahalf ^ ((row1 >> 2) & 1)) << 4));
    // B-fragment indices
    const int tl = lane >> 3;
    const int b_crem = (tl & 1) * 8 + (lane & 7);
    const int b_drem = (tl >> 1) * 8;

    // triple buffers per group
    char* xsA[3];
    uint32_t xbA[3];
#pragma unroll
    for (int k = 0; k < 3; k++) {
        xsA[k] = smem + SM_X + k * 16384 + grp * 8192;
        xbA[k] = sb + SM_X + (uint32_t)(k * 16384 + grp * 8192);
    }

    // ---- stage all three W ONCE via identity cp.async ----
#pragma unroll
    for (int i = 0; i < 24; i++) {
        const uint32_t dst = sb + (uint32_t)(tid * 16 + i * 4096);
        const char* src = g_wh + tid * 16 + i * 4096;
        asm volatile("cp.async.cg.shared.global [%0], [%1], 16;" :: "r"(dst), "l"(src));
    }
    asm volatile("cp.async.commit_group;" ::: "memory");
    asm volatile("cp.async.wait_group 0;" ::: "memory");
    __syncthreads();

    const int r0 = warp_m * 32 + (lane >> 2);
    const float bq0 = bq[r0], bq1 = bq[r0 + 8], bq2 = bq[r0 + 16], bq3 = bq[r0 + 24];
    const float bvr[4] = {bv[r0], bv[r0 + 8], bv[r0 + 16], bv[r0 + 24]};

    // ---- persistent tile loop ----
    for (int t = blockIdx.x; t < N_TILES; t += GRID_X) {
        const int b = t >> 8;
        const int dt = (t & 255) * D_TILE + grp * 32;
        const long kvbase = (long)(b * Cn) * Sn * Dn + dt;

        float4 pf[8];

        // stage q -> buf0
        pf_load(pf, q + (long)b * Cn * Dn + dt, (long)Dn, wt);
        pf_store(xsA[0], pf, wt);
        grp_bar(grp);

        // kv0 LDG covered by Q projection
        pf_load(pf, kv + kvbase, (long)Sn * Dn, wt);

        float qp[2][4][4];
        proj(sb + SM_WQ, xbA[0], aw0, aw1, b_crem, b_drem, qp);
#pragma unroll
        for (int n = 0; n < 4; n++) {
            qp[0][n][0] += bq0; qp[0][n][1] += bq0; qp[0][n][2] += bq1; qp[0][n][3] += bq1;
            qp[1][n][0] += bq2; qp[1][n][1] += bq2; qp[1][n][2] += bq3; qp[1][n][3] += bq3;
        }

        float acc[2][4][4], den[2][4][2];
#pragma unroll
        for (int tt = 0; tt < 2; tt++)
#pragma unroll
            for (int n = 0; n < 4; n++) {
                acc[tt][n][0] = acc[tt][n][1] = acc[tt][n][2] = acc[tt][n][3] = 0.0f;
                den[tt][n][0] = den[tt][n][1] = 0.0f;
            }

        pf_store(xsA[1], pf, wt);   // kv0 -> buf1
        grp_bar(grp);

        // pipeline prologue: K + softmax of sample 0 (kv1 LDG covered by projK)
        pf_load(pf, kv + kvbase + (long)Dn, (long)Sn * Dn, wt);

        float w_cur[2][4][2];
        {
            float kp[2][4][4];
            proj(sb + SM_WK, xbA[1], aw0, aw1, b_crem, b_drem, kp);
            softmax_head(qp, kp, w_cur, den);
        }
        pf_store(xsA[2], pf, wt);   // kv1 -> buf2
        grp_bar(grp);

        // rotating buffer pointers: bV = sample s, bK = sample s+1, bS = store target (s+2)
        uint32_t bV = xbA[1], bK = xbA[2], bS = xbA[0];
        char *cS = xsA[0], *cN1 = xsA[1], *cN2 = xsA[2];

        for (int s = 0; s < 8; s++) {
            if (s < 7)
                pf_load(pf, kv + kvbase + (long)(s + 2) * Dn, (long)Sn * Dn, wt);

            // K of sample s+1, softmax (shfl/exp) sandwiched before V MMAs:
            // ptxas fills shfl latency with projV's ldsm/MMA issue.
            float w_next[2][4][2];
            {
                float kp[2][4][4];
                proj(sb + SM_WK, bK, aw0, aw1, b_crem, b_drem, kp);
                softmax_head(qp, kp, w_next, den);
            }

            // V of sample s + accumulate with w_cur
            {
                float vp[2][4][4];
                proj(sb + SM_WV, bV, aw0, aw1, b_crem, b_drem, vp);
                acc_apply(acc, w_cur, vp);
            }

            if (s < 7) pf_store(cS, pf, wt);

#pragma unroll
            for (int tt = 0; tt < 2; tt++)
#pragma unroll
                for (int n = 0; n < 4; n++) {
                    w_cur[tt][n][0] = w_next[tt][n][0];
                    w_cur[tt][n][1] = w_next[tt][n][1];
                }

            // rotate buffers: (bV,bK,bS) <- (bK,bS,bV), char* trio likewise
            uint32_t tb = bV; bV = bK; bK = bS; bS = tb;
            char* tc = cS; cS = cN1; cN1 = cN2; cN2 = tc;

            grp_bar(grp);
        }

        // epilogue: V of sample 8 (bV now = its buffer)
        {
            float vp[2][4][4];
            proj(sb + SM_WV, bV, aw0, aw1, b_crem, b_drem, vp);
            acc_apply(acc, w_cur, vp);
        }
        grp_bar(grp);   // buf0's readers done before next tile's q store

        // output: out = acc/den + bv
#pragma unroll
        for (int tt = 0; tt < 2; tt++)
#pragma unroll
            for (int n = 0; n < 4; n++) {
                const int row = warp_m * 32 + tt * 16 + (lane >> 2);
                float* dst = out + ((long)(b * Cn + row)) * Dn + dt + n * 8 + (lane & 3) * 2;
                const float de = den[tt][n][0], dz = den[tt][n][1];
                float2 v0 = make_float2(acc[tt][n][0] / de + bvr[tt * 2],
                                        acc[tt][n][1] / dz + bvr[tt * 2]);
                float2 v1 = make_float2(acc[tt][n][2] / de + bvr[tt * 2 + 1],
                                        acc[tt][n][3] / dz + bvr[tt * 2 + 1]);
                *reinterpret_cast<float2*>(dst) = v0;
                *reinterpret_cast<float2*>(dst + (long)8 * Dn) = v1;
            }
    }
}

extern "C" void kernel_launch(void* const* d_in, const int* in_sizes, int n_in,
                              void* d_out, int out_size) {
    const float* q  = (const float*)d_in[0];
    const float* kv = (const float*)d_in[1];
    const float* Wq = (const float*)d_in[2];
    const float* bq = (const float*)d_in[3];
    const float* Wk = (const float*)d_in[4];
    // d_in[5] = bk: unused (softmax-invariant)
    const float* Wv = (const float*)d_in[6];
    const float* bv = (const float*)d_in[7];
    float* out = (float*)d_out;

    prep_w<<<48, 256>>>(Wq, Wk, Wv);

    cudaFuncSetAttribute(deform_attn_hmma,
                         cudaFuncAttributeMaxDynamicSharedMemorySize, SM_TOTAL);
    deform_attn_hmma<<<dim3(GRID_X, 1), NT, SM_TOTAL>>>(q, kv, bq, bv, out);
}